// round 14
// baseline (speedup 1.0000x reference)
#include <cuda_runtime.h>
#include <cuda_fp16.h>
#include <cstdint>

#define DD 128
#define NMAX 100000
#define EMAX 1600000
#define WSCALE 256.0f
#define WINV   (1.0f / 256.0f)

// ---------------- static scratch ----------------
__device__ int   g_cnt[NMAX];
__device__ int   g_rowptr[NMAX + 1];
__device__ int   g_col[EMAX];
__device__ __align__(16) float g_dinv[NMAX];
__device__ int   g_blocksums[256];
__device__ __align__(16) float g_M[DD * DD];     // lin@fc
__device__ __align__(16) float g_P[DD * DD];     // gin_w1 @ gin_w2
__device__ __align__(16) float g_Wg[DD * DD];    // gcn_w2 @ M
__device__ __align__(16) float g_Wn2[DD * DD];   // gin_w2 @ M
__device__ __align__(16) float g_Wn[DD * DD];    // P @ M
__device__ __align__(16) float g_c0a[DD];
__device__ __align__(16) float g_c0[DD];
__device__ __align__(16) float g_c1[DD];
// fp16 weight images [matrix][hi/lo], [n][k] layout, pre-scaled by WSCALE
// 0=gcn_w1, 1=Wg, 2=Wn
__device__ __align__(16) __half g_wimg[3][2][16384];
// fp16 panels: 1=A1=X+aggU(X), 2=h, 4=Xh (fp16 copy of X); 0,3 unused now
__device__ __align__(16) __half g_Pf[5][(size_t)NMAX * DD];

// ---------------- PTX helpers ----------------
__device__ __forceinline__ uint32_t smem_u32(const void* p) {
    uint32_t a;
    asm("{ .reg .u64 t; cvta.to.shared.u64 t, %1; cvt.u32.u64 %0, t; }" : "=r"(a) : "l"(p));
    return a;
}
__device__ __forceinline__ void ldsm4(uint32_t* r, uint32_t addr) {
    asm volatile("ldmatrix.sync.aligned.m8n8.x4.shared.b16 {%0,%1,%2,%3}, [%4];"
                 : "=r"(r[0]), "=r"(r[1]), "=r"(r[2]), "=r"(r[3]) : "r"(addr));
}
__device__ __forceinline__ void mma_f16(float* c, const uint32_t* a, const uint32_t* b) {
    asm volatile("mma.sync.aligned.m16n8k16.row.col.f32.f16.f16.f32 "
                 "{%0,%1,%2,%3}, {%4,%5,%6,%7}, {%8,%9}, {%0,%1,%2,%3};"
                 : "+f"(c[0]), "+f"(c[1]), "+f"(c[2]), "+f"(c[3])
                 : "r"(a[0]), "r"(a[1]), "r"(a[2]), "r"(a[3]), "r"(b[0]), "r"(b[1]));
}
__device__ __forceinline__ void cpasync16(uint32_t dst, const void* src) {
    asm volatile("cp.async.cg.shared.global [%0], [%1], 16;"
                 :: "r"(dst), "l"(src) : "memory");
}
__device__ __forceinline__ void cp_commit() { asm volatile("cp.async.commit_group;" ::: "memory"); }
template <int N> __device__ __forceinline__ void cp_wait() {
    asm volatile("cp.async.wait_group %0;" :: "n"(N) : "memory");
}
// conflict-free chunk16 tile: row r (0..127) of 16 fp16 = 2x16B pieces, stride 32B
__device__ __forceinline__ uint32_t swz(int r, int p) {
    return (uint32_t)(r * 32 + ((p ^ (r & 1) ^ ((r >> 2) & 1)) << 4));
}
__device__ __forceinline__ uint32_t h2u(__half2 h) { return *(uint32_t*)&h; }
__device__ __forceinline__ void storeh4(__half* p, size_t idx, float4 v) {
    __half2 a = __floats2half2_rn(v.x, v.y);
    __half2 b = __floats2half2_rn(v.z, v.w);
    *(uint2*)(p + idx) = make_uint2(h2u(a), h2u(b));
}
__device__ __forceinline__ float4 loadh4(const __half* p, size_t idx) {
    uint2 u = *(const uint2*)(p + idx);
    float2 fa = __half22float2(*(__half2*)&u.x);
    float2 fb = __half22float2(*(__half2*)&u.y);
    return make_float4(fa.x, fa.y, fb.x, fb.y);
}
// store float4 as 4 halves into the swizzled A-tile (8B per lane)
__device__ __forceinline__ void store_smemA(unsigned char* sA, int r, int lane, float4 v) {
    __half2 a = __floats2half2_rn(v.x, v.y);
    __half2 b = __floats2half2_rn(v.z, v.w);
    uint32_t off = ((uint32_t)(lane >> 2) << 12) + swz(r, (lane >> 1) & 1) + ((lane & 1) << 3);
    *(uint2*)(sA + off) = make_uint2(h2u(a), h2u(b));
}

// ---------------- CSR build ----------------
__global__ void k_zero_cnt(int n) {
    int i = blockIdx.x * blockDim.x + threadIdx.x;
    if (i < n) g_cnt[i] = 0;
}
__global__ void k_hist(const int* __restrict__ ei, int E, int n) {
    int e = blockIdx.x * blockDim.x + threadIdx.x;
    if (e < E) {
        int d = ei[E + e];
        if (d >= 0 && d < n) atomicAdd(&g_cnt[d], 1);
    }
}
__global__ void k_scan1(int n) {
    __shared__ int s[1024];
    int i = blockIdx.x * 1024 + threadIdx.x;
    int v = (i < n) ? g_cnt[i] : 0;
    s[threadIdx.x] = v;
    __syncthreads();
    for (int off = 1; off < 1024; off <<= 1) {
        int t = (threadIdx.x >= off) ? s[threadIdx.x - off] : 0;
        __syncthreads();
        s[threadIdx.x] += t;
        __syncthreads();
    }
    if (i < n) g_rowptr[i] = s[threadIdx.x] - v;
    if (threadIdx.x == 1023) g_blocksums[blockIdx.x] = s[1023];
}
__global__ void k_scan2(int nb) {
    __shared__ int s[256];
    int t = threadIdx.x;
    int v = (t < nb) ? g_blocksums[t] : 0;
    s[t] = v;
    __syncthreads();
    for (int off = 1; off < 256; off <<= 1) {
        int u = (t >= off) ? s[t - off] : 0;
        __syncthreads();
        s[t] += u;
        __syncthreads();
    }
    if (t < nb) g_blocksums[t] = s[t] - v;
}
__global__ void k_scan3(int n, int E) {
    int i = blockIdx.x * blockDim.x + threadIdx.x;
    if (i < n) {
        g_rowptr[i] += g_blocksums[i >> 10];
        g_dinv[i] = rsqrtf((float)g_cnt[i] + 1.0f);
        g_cnt[i] = 0;
    }
    if (i == 0) g_rowptr[n] = E;
}
__global__ void k_fill(const int* __restrict__ ei, int E, int n) {
    int e = blockIdx.x * blockDim.x + threadIdx.x;
    if (e < E) {
        int s = ei[e];
        int d = ei[E + e];
        if (s >= 0 && s < n && d >= 0 && d < n) {
            int pos = g_rowptr[d] + atomicAdd(&g_cnt[d], 1);
            g_col[pos] = s;
        }
    }
}
// after k_fill, g_cnt[i] == incoming degree again (used by l2 epilogue)

// ---------------- X -> fp16 panel ----------------
__global__ void k_xconv(const float* __restrict__ X, int total4) {
    int i = blockIdx.x * 256 + threadIdx.x;
    if (i < total4) {
        float4 v = ((const float4*)X)[i];
        storeh4(g_Pf[4], (size_t)i * 4, v);
    }
}

// ---------------- weight folding ----------------
__global__ void k_prepA(const float* __restrict__ lin_w, const float* __restrict__ lin_b,
                        const float* __restrict__ fc_w, const float* __restrict__ fc_b,
                        const float* __restrict__ gin_w1, const float* __restrict__ gin_w2) {
    int c = threadIdx.x;
    int b = blockIdx.x;
    if (b < DD) {
        float a = 0.f;
        #pragma unroll 8
        for (int k = 0; k < DD; k++) a += lin_w[b * DD + k] * fc_w[k * DD + c];
        g_M[b * DD + c] = a;
    } else if (b < 2 * DD) {
        int r = b - DD;
        float a = 0.f;
        #pragma unroll 8
        for (int k = 0; k < DD; k++) a += gin_w1[r * DD + k] * gin_w2[k * DD + c];
        g_P[r * DD + c] = a;
    } else {
        float a = 0.f;
        #pragma unroll 8
        for (int k = 0; k < DD; k++) a += lin_b[k] * fc_w[k * DD + c];
        g_c0a[c] = 2.f * a + fc_b[c];
    }
}
__global__ void k_prepB(const float* __restrict__ gcn_w2, const float* __restrict__ gin_w2,
                        const float* __restrict__ gcn_b2, const float* __restrict__ gin_b2) {
    int c = threadIdx.x;
    int b = blockIdx.x;
    if (b < DD) {
        float a = 0.f;
        #pragma unroll 8
        for (int k = 0; k < DD; k++) a += gcn_w2[b * DD + k] * g_M[k * DD + c];
        g_Wg[b * DD + c] = a;
    } else if (b < 2 * DD) {
        int r = b - DD;
        float a = 0.f;
        #pragma unroll 8
        for (int k = 0; k < DD; k++) a += gin_w2[r * DD + k] * g_M[k * DD + c];
        g_Wn2[r * DD + c] = a;
    } else if (b < 3 * DD) {
        int r = b - 2 * DD;
        float a = 0.f;
        #pragma unroll 8
        for (int k = 0; k < DD; k++) a += g_P[r * DD + k] * g_M[k * DD + c];
        g_Wn[r * DD + c] = a;
    } else {
        float a = 0.f;
        #pragma unroll 8
        for (int k = 0; k < DD; k++)
            a += (gcn_b2[k] + gin_b2[k]) * g_M[k * DD + c];
        g_c0[c] = a + g_c0a[c];
    }
}
__global__ void k_wprep(const float* __restrict__ gcn_w1) {
    int mat = blockIdx.y;
    int i = blockIdx.x * 256 + threadIdx.x;
    if (i >= 16384) return;
    int k = i >> 7, nn = i & 127;
    const float* W = (mat == 0) ? gcn_w1 : (mat == 1) ? g_Wg : g_Wn;
    float x = W[k * 128 + nn] * WSCALE;
    __half hi = __float2half_rn(x);
    __half lo = __float2half_rn(x - __half2float(hi));
    g_wimg[mat][0][nn * 128 + k] = hi;
    g_wimg[mat][1][nn * 128 + k] = lo;
}
__global__ void k_c1(const float* __restrict__ gin_b1) {
    int c = threadIdx.x;
    float a = 0.f;
    #pragma unroll 8
    for (int k = 0; k < DD; k++) a += gin_b1[k] * g_Wn2[k * DD + c];
    g_c1[c] = a;
}

// ---------------- fused agg + GEMM building blocks ----------------
// GEMM over a resident swizzled A-tile (8 chunks of K=16), W hi/lo double-buffered.
// wimg index runtime (2 call sites per l2 kernel).
__device__ __forceinline__ void gemm_resident(int wi, unsigned char* sA, unsigned char* sW,
                                              float acc[2][8][4],
                                              int wm, int wn, int lane, int tid) {
    uint32_t Abase = smem_u32(sA);
    uint32_t Wbase = smem_u32(sW);
    int sr = tid >> 1, sp = tid & 1;
    uint32_t soff = swz(sr, sp);
    size_t s_wsrc = (size_t)sr * 128 + sp * 8;

    // stage chunk 0
    {
        cpasync16(Wbase + soff,        g_wimg[wi][0] + s_wsrc);
        cpasync16(Wbase + 4096 + soff, g_wimg[wi][1] + s_wsrc);
        cp_commit();
    }
    for (int c = 0; c < 8; c++) {
        if (c + 1 < 8) {
            uint32_t b = Wbase + ((c + 1) & 1) * 8192;
            size_t kw = s_wsrc + (size_t)(c + 1) * 16;
            cpasync16(b + soff,        g_wimg[wi][0] + kw);
            cpasync16(b + 4096 + soff, g_wimg[wi][1] + kw);
            cp_commit();
            cp_wait<1>();
        } else {
            cp_wait<0>();
        }
        __syncthreads();

        uint32_t aB = Abase + c * 4096;
        uint32_t wB = Wbase + (c & 1) * 8192;
        uint32_t a[2][4];
        #pragma unroll
        for (int mi = 0; mi < 2; mi++) {
            int row = wm * 32 + mi * 16 + (lane & 15);
            ldsm4(a[mi], aB + swz(row, lane >> 4));
        }
        #pragma unroll
        for (int term = 0; term < 2; term++) {
            uint32_t wb = wB + term * 4096;
            uint32_t bf[8][2];
            #pragma unroll
            for (int q = 0; q < 4; q++) {
                int rown = wn * 64 + q * 16 + ((lane >> 4) << 3) + (lane & 7);
                uint32_t r4[4];
                ldsm4(r4, wb + swz(rown, (lane >> 3) & 1));
                bf[q * 2 + 0][0] = r4[0]; bf[q * 2 + 0][1] = r4[1];
                bf[q * 2 + 1][0] = r4[2]; bf[q * 2 + 1][1] = r4[3];
            }
            #pragma unroll
            for (int mi = 0; mi < 2; mi++)
                #pragma unroll
                for (int nj = 0; nj < 8; nj++)
                    mma_f16(acc[mi][nj], a[mi], bf[nj]);
        }
        __syncthreads();
    }
}

// ---------------- fused layer 1: agg(Xh) + GEMM(gcn_w1) -> h panel ----------------
__global__ void __launch_bounds__(256, 2) k_fused_l1(const float* __restrict__ b1, int n) {
    __shared__ __align__(1024) unsigned char sA[32768];
    __shared__ __align__(1024) unsigned char sW[16384];
    int tid = threadIdx.x, lane = tid & 31, wid = tid >> 5;
    int wm = wid & 3, wn = wid >> 2;
    int row0 = blockIdx.x * 128;

    // aggregation phase: warp handles 16 consecutive nodes
    for (int i = 0; i < 16; i++) {
        int node = row0 + wid * 16 + i;
        if (node >= n) break;
        int r = wid * 16 + i;
        int e = g_rowptr[node], end = g_rowptr[node + 1];
        float4 aw = make_float4(0, 0, 0, 0), au = make_float4(0, 0, 0, 0);
        for (; e + 4 <= end; e += 4) {
            int j0 = g_col[e], j1 = g_col[e + 1], j2 = g_col[e + 2], j3 = g_col[e + 3];
            float d0 = g_dinv[j0], d1 = g_dinv[j1], d2 = g_dinv[j2], d3 = g_dinv[j3];
            float4 v0 = loadh4(g_Pf[4], (size_t)j0 * 128 + lane * 4);
            float4 v1 = loadh4(g_Pf[4], (size_t)j1 * 128 + lane * 4);
            float4 v2 = loadh4(g_Pf[4], (size_t)j2 * 128 + lane * 4);
            float4 v3 = loadh4(g_Pf[4], (size_t)j3 * 128 + lane * 4);
            aw.x += d0 * v0.x + d1 * v1.x + d2 * v2.x + d3 * v3.x;
            aw.y += d0 * v0.y + d1 * v1.y + d2 * v2.y + d3 * v3.y;
            aw.z += d0 * v0.z + d1 * v1.z + d2 * v2.z + d3 * v3.z;
            aw.w += d0 * v0.w + d1 * v1.w + d2 * v2.w + d3 * v3.w;
            au.x += v0.x + v1.x + v2.x + v3.x;
            au.y += v0.y + v1.y + v2.y + v3.y;
            au.z += v0.z + v1.z + v2.z + v3.z;
            au.w += v0.w + v1.w + v2.w + v3.w;
        }
        for (; e < end; e++) {
            int j = g_col[e];
            float dj = g_dinv[j];
            float4 v = loadh4(g_Pf[4], (size_t)j * 128 + lane * 4);
            aw.x += dj * v.x; aw.y += dj * v.y; aw.z += dj * v.z; aw.w += dj * v.w;
            au.x += v.x;      au.y += v.y;      au.z += v.z;      au.w += v.w;
        }
        float di = g_dinv[node], dii = di * di;
        size_t iw = (size_t)node * 128 + lane * 4;
        float4 xi = loadh4(g_Pf[4], iw);
        float4 ow, ou;
        ow.x = di * aw.x + dii * xi.x; ow.y = di * aw.y + dii * xi.y;
        ow.z = di * aw.z + dii * xi.z; ow.w = di * aw.w + dii * xi.w;
        ou.x = au.x + xi.x; ou.y = au.y + xi.y; ou.z = au.z + xi.z; ou.w = au.w + xi.w;
        storeh4(g_Pf[1], iw, ou);          // A1 -> global (layer-2 input)
        store_smemA(sA, r, lane, ow);      // aggW -> resident A-tile
    }

    float acc[2][8][4];
    #pragma unroll
    for (int i = 0; i < 2; i++)
        #pragma unroll
        for (int j = 0; j < 8; j++)
            #pragma unroll
            for (int q = 0; q < 4; q++) acc[i][j][q] = 0.f;

    gemm_resident(0, sA, sW, acc, wm, wn, lane, tid);

    // epilogue: relu(acc*WINV + b1) -> h panel (fp16)
    int rbase = row0 + wm * 32 + (lane >> 2);
    int cbase = wn * 64 + (lane & 3) * 2;
    #pragma unroll
    for (int mi = 0; mi < 2; mi++) {
        #pragma unroll
        for (int half = 0; half < 2; half++) {
            int gr = rbase + mi * 16 + half * 8;
            if (gr >= n) continue;
            #pragma unroll
            for (int nj = 0; nj < 8; nj++) {
                int col = cbase + nj * 8;
                float v0 = fmaxf(acc[mi][nj][half * 2 + 0] * WINV + b1[col], 0.f);
                float v1 = fmaxf(acc[mi][nj][half * 2 + 1] * WINV + b1[col + 1], 0.f);
                __half2 hh = __floats2half2_rn(v0, v1);
                *(__half2*)&g_Pf[2][(size_t)gr * 128 + col] = hh;
            }
        }
    }
}

// ---------------- fused layer 2: agg(h)+GEMM(Wg), agg(A1)+GEMM(Wn) -> out ----------------
__global__ void __launch_bounds__(256, 2) k_fused_l2(float* __restrict__ out, int n) {
    __shared__ __align__(1024) unsigned char sA[32768];
    __shared__ __align__(1024) unsigned char sW[16384];
    int tid = threadIdx.x, lane = tid & 31, wid = tid >> 5;
    int wm = wid & 3, wn = wid >> 2;
    int row0 = blockIdx.x * 128;

    float acc[2][8][4];
    #pragma unroll
    for (int i = 0; i < 2; i++)
        #pragma unroll
        for (int j = 0; j < 8; j++)
            #pragma unroll
            for (int q = 0; q < 4; q++) acc[i][j][q] = 0.f;

    // ---- pass 0: aggW(h)+self -> A-tile; GEMM with Wg (wimg 1) ----
    for (int i = 0; i < 16; i++) {
        int node = row0 + wid * 16 + i;
        if (node >= n) break;
        int r = wid * 16 + i;
        int e = g_rowptr[node], end = g_rowptr[node + 1];
        float4 aw = make_float4(0, 0, 0, 0);
        for (; e + 4 <= end; e += 4) {
            int j0 = g_col[e], j1 = g_col[e + 1], j2 = g_col[e + 2], j3 = g_col[e + 3];
            float d0 = g_dinv[j0], d1 = g_dinv[j1], d2 = g_dinv[j2], d3 = g_dinv[j3];
            float4 v0 = loadh4(g_Pf[2], (size_t)j0 * 128 + lane * 4);
            float4 v1 = loadh4(g_Pf[2], (size_t)j1 * 128 + lane * 4);
            float4 v2 = loadh4(g_Pf[2], (size_t)j2 * 128 + lane * 4);
            float4 v3 = loadh4(g_Pf[2], (size_t)j3 * 128 + lane * 4);
            aw.x += d0 * v0.x + d1 * v1.x + d2 * v2.x + d3 * v3.x;
            aw.y += d0 * v0.y + d1 * v1.y + d2 * v2.y + d3 * v3.y;
            aw.z += d0 * v0.z + d1 * v1.z + d2 * v2.z + d3 * v3.z;
            aw.w += d0 * v0.w + d1 * v1.w + d2 * v2.w + d3 * v3.w;
        }
        for (; e < end; e++) {
            int j = g_col[e];
            float dj = g_dinv[j];
            float4 v = loadh4(g_Pf[2], (size_t)j * 128 + lane * 4);
            aw.x += dj * v.x; aw.y += dj * v.y; aw.z += dj * v.z; aw.w += dj * v.w;
        }
        float di = g_dinv[node], dii = di * di;
        float4 hi = loadh4(g_Pf[2], (size_t)node * 128 + lane * 4);
        float4 ow;
        ow.x = di * aw.x + dii * hi.x; ow.y = di * aw.y + dii * hi.y;
        ow.z = di * aw.z + dii * hi.z; ow.w = di * aw.w + dii * hi.w;
        store_smemA(sA, r, lane, ow);
    }
    gemm_resident(1, sA, sW, acc, wm, wn, lane, tid);
    // (gemm_resident ends with __syncthreads — safe to overwrite A-tile)

    // ---- pass 1: A2 = A1 + aggU(A1) -> A-tile; GEMM with Wn (wimg 2) ----
    for (int i = 0; i < 16; i++) {
        int node = row0 + wid * 16 + i;
        if (node >= n) break;
        int r = wid * 16 + i;
        int e = g_rowptr[node], end = g_rowptr[node + 1];
        float4 au = make_float4(0, 0, 0, 0);
        for (; e + 4 <= end; e += 4) {
            int j0 = g_col[e], j1 = g_col[e + 1], j2 = g_col[e + 2], j3 = g_col[e + 3];
            float4 a0 = loadh4(g_Pf[1], (size_t)j0 * 128 + lane * 4);
            float4 a1 = loadh4(g_Pf[1], (size_t)j1 * 128 + lane * 4);
            float4 a2 = loadh4(g_Pf[1], (size_t)j2 * 128 + lane * 4);
            float4 a3 = loadh4(g_Pf[1], (size_t)j3 * 128 + lane * 4);
            au.x += a0.x + a1.x + a2.x + a3.x;
            au.y += a0.y + a1.y + a2.y + a3.y;
            au.z += a0.z + a1.z + a2.z + a3.z;
            au.w += a0.w + a1.w + a2.w + a3.w;
        }
        for (; e < end; e++) {
            int j = g_col[e];
            float4 av = loadh4(g_Pf[1], (size_t)j * 128 + lane * 4);
            au.x += av.x; au.y += av.y; au.z += av.z; au.w += av.w;
        }
        float4 ai = loadh4(g_Pf[1], (size_t)node * 128 + lane * 4);
        float4 ou = make_float4(au.x + ai.x, au.y + ai.y, au.z + ai.z, au.w + ai.w);
        store_smemA(sA, r, lane, ou);
    }
    gemm_resident(2, sA, sW, acc, wm, wn, lane, tid);

    // epilogue: acc*WINV + (deg+1)*c1 + c0 -> out (fp32)
    int rbase = row0 + wm * 32 + (lane >> 2);
    int cbase = wn * 64 + (lane & 3) * 2;
    #pragma unroll
    for (int mi = 0; mi < 2; mi++) {
        #pragma unroll
        for (int half = 0; half < 2; half++) {
            int gr = rbase + mi * 16 + half * 8;
            if (gr >= n) continue;
            float s = (float)(g_cnt[gr] + 1);
            #pragma unroll
            for (int nj = 0; nj < 8; nj++) {
                int col = cbase + nj * 8;
                float v0 = acc[mi][nj][half * 2 + 0] * WINV + s * g_c1[col]     + g_c0[col];
                float v1 = acc[mi][nj][half * 2 + 1] * WINV + s * g_c1[col + 1] + g_c0[col + 1];
                *(float2*)&out[(size_t)gr * 128 + col] = make_float2(v0, v1);
            }
        }
    }
}

// ---------------- launch ----------------
extern "C" void kernel_launch(void* const* d_in, const int* in_sizes, int n_in,
                              void* d_out, int out_size) {
    const float* X      = (const float*)d_in[0];
    const int*   ei     = (const int*)d_in[1];
    const float* gcn_w1 = (const float*)d_in[2];
    const float* gcn_b1 = (const float*)d_in[3];
    const float* gcn_w2 = (const float*)d_in[4];
    const float* gcn_b2 = (const float*)d_in[5];
    const float* gin_w1 = (const float*)d_in[6];
    const float* gin_b1 = (const float*)d_in[7];
    const float* gin_w2 = (const float*)d_in[8];
    const float* gin_b2 = (const float*)d_in[9];
    const float* lin_w  = (const float*)d_in[10];
    const float* lin_b  = (const float*)d_in[11];
    const float* fc_w   = (const float*)d_in[12];
    const float* fc_b   = (const float*)d_in[13];
    float*       out    = (float*)d_out;

    int N = in_sizes[0] / DD;
    int E = in_sizes[1] / 2;

    int nb = (N + 1023) / 1024;
    int gN = (N + 255) / 256;
    int gE = (E + 255) / 256;
    int gG = (N + 127) / 128;
    int gX = (N * 32 + 255) / 256;

    // X fp16 conversion
    k_xconv<<<gX, 256>>>(X, N * 32);

    // CSR build
    k_zero_cnt<<<gN, 256>>>(N);
    k_hist<<<gE, 256>>>(ei, E, N);
    k_scan1<<<nb, 1024>>>(N);
    k_scan2<<<1, 256>>>(nb);
    k_scan3<<<gN, 256>>>(N, E);
    k_fill<<<gE, 256>>>(ei, E, N);

    // weight folding + fp16 images
    k_prepA<<<2 * DD + 1, DD>>>(lin_w, lin_b, fc_w, fc_b, gin_w1, gin_w2);
    k_prepB<<<3 * DD + 1, DD>>>(gcn_w2, gin_w2, gcn_b2, gin_b2);
    k_c1<<<1, DD>>>(gin_b1);
    k_wprep<<<dim3(64, 3), 256>>>(gcn_w1);

    // fused layers
    k_fused_l1<<<gG, 256>>>(gcn_b1, N);
    k_fused_l2<<<gG, 256>>>(out, N);
}

// round 15
// speedup vs baseline: 1.5379x; 1.5379x over previous
#include <cuda_runtime.h>
#include <cuda_fp16.h>
#include <cstdint>

#define DD 128
#define NMAX 100000
#define EMAX 1600000
#define WSCALE 256.0f
#define WINV   (1.0f / 256.0f)

// ---------------- static scratch ----------------
__device__ int   g_cnt[NMAX];
__device__ int   g_rowptr[NMAX + 1];
__device__ int   g_col[EMAX];
__device__ __align__(16) float g_dinv[NMAX];
__device__ int   g_blocksums[256];
__device__ __align__(16) float g_M[DD * DD];     // lin@fc
__device__ __align__(16) float g_P[DD * DD];     // gin_w1 @ gin_w2
__device__ __align__(16) float g_Wg[DD * DD];    // gcn_w2 @ M
__device__ __align__(16) float g_Wn2[DD * DD];   // gin_w2 @ M
__device__ __align__(16) float g_Wn[DD * DD];    // P @ M
__device__ __align__(16) float g_c0a[DD];
__device__ __align__(16) float g_c0[DD];
__device__ __align__(16) float g_c1[DD];
// fp16 weight images [matrix][hi/lo], [n][k] layout, pre-scaled by WSCALE
// 0=gcn_w1, 1=Wg, 2=Wn
__device__ __align__(16) __half g_wimg[3][2][16384];
// fp16 panels (standard [node][128] layout): 0=aggW(X)/aggW(h), 3=A2
__device__ __align__(16) __half g_Pf[4][(size_t)NMAX * DD];
// interleaved HA panel: [node][lane*8: h0..h3, a0..a3] (256 halves per node)
__device__ __align__(16) __half g_HA[(size_t)NMAX * 256];

// ---------------- PTX helpers ----------------
__device__ __forceinline__ uint32_t smem_u32(const void* p) {
    uint32_t a;
    asm("{ .reg .u64 t; cvta.to.shared.u64 t, %1; cvt.u32.u64 %0, t; }" : "=r"(a) : "l"(p));
    return a;
}
__device__ __forceinline__ void ldsm4(uint32_t* r, uint32_t addr) {
    asm volatile("ldmatrix.sync.aligned.m8n8.x4.shared.b16 {%0,%1,%2,%3}, [%4];"
                 : "=r"(r[0]), "=r"(r[1]), "=r"(r[2]), "=r"(r[3]) : "r"(addr));
}
__device__ __forceinline__ void mma_f16(float* c, const uint32_t* a, const uint32_t* b) {
    asm volatile("mma.sync.aligned.m16n8k16.row.col.f32.f16.f16.f32 "
                 "{%0,%1,%2,%3}, {%4,%5,%6,%7}, {%8,%9}, {%0,%1,%2,%3};"
                 : "+f"(c[0]), "+f"(c[1]), "+f"(c[2]), "+f"(c[3])
                 : "r"(a[0]), "r"(a[1]), "r"(a[2]), "r"(a[3]), "r"(b[0]), "r"(b[1]));
}
__device__ __forceinline__ void cpasync16(uint32_t dst, const void* src, int szbytes) {
    asm volatile("cp.async.cg.shared.global [%0], [%1], 16, %2;"
                 :: "r"(dst), "l"(src), "r"(szbytes) : "memory");
}
__device__ __forceinline__ void cp_commit() { asm volatile("cp.async.commit_group;" ::: "memory"); }
template <int N> __device__ __forceinline__ void cp_wait() {
    asm volatile("cp.async.wait_group %0;" :: "n"(N) : "memory");
}
// conflict-free chunk16 tile: row r (0..127) of 16 fp16 = 2x16B pieces, stride 32B
__device__ __forceinline__ uint32_t swz(int r, int p) {
    return (uint32_t)(r * 32 + ((p ^ (r & 1) ^ ((r >> 2) & 1)) << 4));
}
__device__ __forceinline__ uint32_t h2u(__half2 h) { return *(uint32_t*)&h; }
__device__ __forceinline__ void storeh4(__half* p, size_t idx, float4 v) {
    __half2 a = __floats2half2_rn(v.x, v.y);
    __half2 b = __floats2half2_rn(v.z, v.w);
    *(uint2*)(p + idx) = make_uint2(h2u(a), h2u(b));
}

// ---------------- CSR build ----------------
__global__ void k_zero_cnt(int n) {
    int i = blockIdx.x * blockDim.x + threadIdx.x;
    if (i < n) g_cnt[i] = 0;
}
__global__ void k_hist(const int* __restrict__ ei, int E, int n) {
    int e = blockIdx.x * blockDim.x + threadIdx.x;
    if (e < E) {
        int d = ei[E + e];
        if (d >= 0 && d < n) atomicAdd(&g_cnt[d], 1);
    }
}
__global__ void k_scan1(int n) {
    __shared__ int s[1024];
    int i = blockIdx.x * 1024 + threadIdx.x;
    int v = (i < n) ? g_cnt[i] : 0;
    s[threadIdx.x] = v;
    __syncthreads();
    for (int off = 1; off < 1024; off <<= 1) {
        int t = (threadIdx.x >= off) ? s[threadIdx.x - off] : 0;
        __syncthreads();
        s[threadIdx.x] += t;
        __syncthreads();
    }
    if (i < n) g_rowptr[i] = s[threadIdx.x] - v;
    if (threadIdx.x == 1023) g_blocksums[blockIdx.x] = s[1023];
}
__global__ void k_scan2(int nb) {
    __shared__ int s[256];
    int t = threadIdx.x;
    int v = (t < nb) ? g_blocksums[t] : 0;
    s[t] = v;
    __syncthreads();
    for (int off = 1; off < 256; off <<= 1) {
        int u = (t >= off) ? s[t - off] : 0;
        __syncthreads();
        s[t] += u;
        __syncthreads();
    }
    if (t < nb) g_blocksums[t] = s[t] - v;
}
__global__ void k_scan3(int n, int E) {
    int i = blockIdx.x * blockDim.x + threadIdx.x;
    if (i < n) {
        g_rowptr[i] += g_blocksums[i >> 10];
        g_dinv[i] = rsqrtf((float)g_cnt[i] + 1.0f);
        g_cnt[i] = 0;
    }
    if (i == 0) g_rowptr[n] = E;
}
__global__ void k_fill(const int* __restrict__ ei, int E, int n) {
    int e = blockIdx.x * blockDim.x + threadIdx.x;
    if (e < E) {
        int s = ei[e];
        int d = ei[E + e];
        if (s >= 0 && s < n && d >= 0 && d < n) {
            int pos = g_rowptr[d] + atomicAdd(&g_cnt[d], 1);
            g_col[pos] = s;
        }
    }
}
// after k_fill, g_cnt[i] == incoming degree again (used by l2 epilogue)

// ---------------- weight folding ----------------
__global__ void k_prepA(const float* __restrict__ lin_w, const float* __restrict__ lin_b,
                        const float* __restrict__ fc_w, const float* __restrict__ fc_b,
                        const float* __restrict__ gin_w1, const float* __restrict__ gin_w2) {
    int c = threadIdx.x;
    int b = blockIdx.x;
    if (b < DD) {
        float a = 0.f;
        #pragma unroll 8
        for (int k = 0; k < DD; k++) a += lin_w[b * DD + k] * fc_w[k * DD + c];
        g_M[b * DD + c] = a;
    } else if (b < 2 * DD) {
        int r = b - DD;
        float a = 0.f;
        #pragma unroll 8
        for (int k = 0; k < DD; k++) a += gin_w1[r * DD + k] * gin_w2[k * DD + c];
        g_P[r * DD + c] = a;
    } else {
        float a = 0.f;
        #pragma unroll 8
        for (int k = 0; k < DD; k++) a += lin_b[k] * fc_w[k * DD + c];
        g_c0a[c] = 2.f * a + fc_b[c];
    }
}
__global__ void k_prepB(const float* __restrict__ gcn_w2, const float* __restrict__ gin_w2,
                        const float* __restrict__ gcn_b2, const float* __restrict__ gin_b2) {
    int c = threadIdx.x;
    int b = blockIdx.x;
    if (b < DD) {
        float a = 0.f;
        #pragma unroll 8
        for (int k = 0; k < DD; k++) a += gcn_w2[b * DD + k] * g_M[k * DD + c];
        g_Wg[b * DD + c] = a;
    } else if (b < 2 * DD) {
        int r = b - DD;
        float a = 0.f;
        #pragma unroll 8
        for (int k = 0; k < DD; k++) a += gin_w2[r * DD + k] * g_M[k * DD + c];
        g_Wn2[r * DD + c] = a;
    } else if (b < 3 * DD) {
        int r = b - 2 * DD;
        float a = 0.f;
        #pragma unroll 8
        for (int k = 0; k < DD; k++) a += g_P[r * DD + k] * g_M[k * DD + c];
        g_Wn[r * DD + c] = a;
    } else {
        float a = 0.f;
        #pragma unroll 8
        for (int k = 0; k < DD; k++)
            a += (gcn_b2[k] + gin_b2[k]) * g_M[k * DD + c];
        g_c0[c] = a + g_c0a[c];
    }
}
__global__ void k_wprep(const float* __restrict__ gcn_w1) {
    int mat = blockIdx.y;
    int i = blockIdx.x * 256 + threadIdx.x;
    if (i >= 16384) return;
    int k = i >> 7, nn = i & 127;
    const float* W = (mat == 0) ? gcn_w1 : (mat == 1) ? g_Wg : g_Wn;
    float x = W[k * 128 + nn] * WSCALE;
    __half hi = __float2half_rn(x);
    __half lo = __float2half_rn(x - __half2float(hi));
    g_wimg[mat][0][nn * 128 + k] = hi;
    g_wimg[mat][1][nn * 128 + k] = lo;
}
__global__ void k_c1(const float* __restrict__ gin_b1) {
    int c = threadIdx.x;
    float a = 0.f;
    #pragma unroll 8
    for (int k = 0; k < DD; k++) a += gin_b1[k] * g_Wn2[k * DD + c];
    g_c1[c] = a;
}

// ---------------- aggregation (warp per node) ----------------
// pass1 (fp32 X input): P0 = aggW(X)+self;  A1 -> HA panel (a-slots)
__global__ void k_agg1(const float* __restrict__ X, int n) {
    int w = (blockIdx.x * blockDim.x + threadIdx.x) >> 5;
    if (w >= n) return;
    int lane = threadIdx.x & 31;
    const float4* Xv = (const float4*)X;
    int e = g_rowptr[w], end = g_rowptr[w + 1];
    float4 aw = make_float4(0, 0, 0, 0), au = make_float4(0, 0, 0, 0);
    for (; e + 4 <= end; e += 4) {
        int j0 = g_col[e], j1 = g_col[e + 1], j2 = g_col[e + 2], j3 = g_col[e + 3];
        float d0 = g_dinv[j0], d1 = g_dinv[j1], d2 = g_dinv[j2], d3 = g_dinv[j3];
        float4 v0 = Xv[(size_t)j0 * 32 + lane];
        float4 v1 = Xv[(size_t)j1 * 32 + lane];
        float4 v2 = Xv[(size_t)j2 * 32 + lane];
        float4 v3 = Xv[(size_t)j3 * 32 + lane];
        aw.x += d0 * v0.x + d1 * v1.x + d2 * v2.x + d3 * v3.x;
        aw.y += d0 * v0.y + d1 * v1.y + d2 * v2.y + d3 * v3.y;
        aw.z += d0 * v0.z + d1 * v1.z + d2 * v2.z + d3 * v3.z;
        aw.w += d0 * v0.w + d1 * v1.w + d2 * v2.w + d3 * v3.w;
        au.x += v0.x + v1.x + v2.x + v3.x;
        au.y += v0.y + v1.y + v2.y + v3.y;
        au.z += v0.z + v1.z + v2.z + v3.z;
        au.w += v0.w + v1.w + v2.w + v3.w;
    }
    for (; e < end; e++) {
        int j = g_col[e];
        float dj = g_dinv[j];
        float4 v = Xv[(size_t)j * 32 + lane];
        aw.x += dj * v.x; aw.y += dj * v.y; aw.z += dj * v.z; aw.w += dj * v.w;
        au.x += v.x;      au.y += v.y;      au.z += v.z;      au.w += v.w;
    }
    float di = g_dinv[w], dii = di * di;
    float4 xi = Xv[(size_t)w * 32 + lane];
    float4 ow, ou;
    ow.x = di * aw.x + dii * xi.x; ow.y = di * aw.y + dii * xi.y;
    ow.z = di * aw.z + dii * xi.z; ow.w = di * aw.w + dii * xi.w;
    ou.x = au.x + xi.x; ou.y = au.y + xi.y; ou.z = au.z + xi.z; ou.w = au.w + xi.w;
    storeh4(g_Pf[0], (size_t)w * 128 + lane * 4, ow);
    storeh4(g_HA, (size_t)w * 256 + lane * 8 + 4, ou);   // A1 into a-slots
}
// pass2: one 16B gather per edge from HA (h+A1 together).
// P0 = aggW(h)+self, P3 = A2 = A1 + aggU(A1)
__global__ void k_agg2(int n) {
    int w = (blockIdx.x * blockDim.x + threadIdx.x) >> 5;
    if (w >= n) return;
    int lane = threadIdx.x & 31;
    int e = g_rowptr[w], end = g_rowptr[w + 1];
    float4 aw = make_float4(0, 0, 0, 0), au = make_float4(0, 0, 0, 0);
    const uint4* HA = (const uint4*)g_HA;   // 8 halves per entry
    for (; e + 2 <= end; e += 2) {
        int j0 = g_col[e], j1 = g_col[e + 1];
        float d0 = g_dinv[j0], d1 = g_dinv[j1];
        uint4 u0 = HA[(size_t)j0 * 32 + lane];
        uint4 u1 = HA[(size_t)j1 * 32 + lane];
        float2 h0a = __half22float2(*(__half2*)&u0.x), h0b = __half22float2(*(__half2*)&u0.y);
        float2 a0a = __half22float2(*(__half2*)&u0.z), a0b = __half22float2(*(__half2*)&u0.w);
        float2 h1a = __half22float2(*(__half2*)&u1.x), h1b = __half22float2(*(__half2*)&u1.y);
        float2 a1a = __half22float2(*(__half2*)&u1.z), a1b = __half22float2(*(__half2*)&u1.w);
        aw.x += d0 * h0a.x + d1 * h1a.x; aw.y += d0 * h0a.y + d1 * h1a.y;
        aw.z += d0 * h0b.x + d1 * h1b.x; aw.w += d0 * h0b.y + d1 * h1b.y;
        au.x += a0a.x + a1a.x; au.y += a0a.y + a1a.y;
        au.z += a0b.x + a1b.x; au.w += a0b.y + a1b.y;
    }
    for (; e < end; e++) {
        int j = g_col[e];
        float dj = g_dinv[j];
        uint4 u = HA[(size_t)j * 32 + lane];
        float2 ha = __half22float2(*(__half2*)&u.x), hb = __half22float2(*(__half2*)&u.y);
        float2 aa = __half22float2(*(__half2*)&u.z), ab = __half22float2(*(__half2*)&u.w);
        aw.x += dj * ha.x; aw.y += dj * ha.y; aw.z += dj * hb.x; aw.w += dj * hb.y;
        au.x += aa.x;      au.y += aa.y;      au.z += ab.x;      au.w += ab.y;
    }
    float di = g_dinv[w], dii = di * di;
    uint4 uw = HA[(size_t)w * 32 + lane];
    float2 hia = __half22float2(*(__half2*)&uw.x), hib = __half22float2(*(__half2*)&uw.y);
    float2 aia = __half22float2(*(__half2*)&uw.z), aib = __half22float2(*(__half2*)&uw.w);
    float4 ow, ou;
    ow.x = di * aw.x + dii * hia.x; ow.y = di * aw.y + dii * hia.y;
    ow.z = di * aw.z + dii * hib.x; ow.w = di * aw.w + dii * hib.y;
    ou.x = au.x + aia.x; ou.y = au.y + aia.y; ou.z = au.z + aib.x; ou.w = au.w + aib.y;
    size_t iw = (size_t)w * 128 + lane * 4;
    storeh4(g_Pf[0], iw, ow);
    storeh4(g_Pf[3], iw, ou);
}

// ---------------- pipelined fp16 warp-mma GEMM (R12 champion version) ----------------
// A fp16 single, W fp16 hi/lo (x WSCALE); 2 terms: A*Wh + A*Wl.
// K chunks of 16; stage = 12KB; double buffered.
// BSEL: 0 = bias_param, 3 = deg-scaled. OUTHA: write h into interleaved HA panel.
template <bool RELU, bool DUAL, int INA1, int INA2, int OUTI, int W1I, int W2I,
          int BSEL, bool OUTF32, bool OUTHA>
__device__ __forceinline__ void tgemm_body(int bx, const float* bias_param,
                                           float* outp, int n, uint32_t sbase) {
    int tid = threadIdx.x, lane = tid & 31, wid = tid >> 5;
    int wm = wid & 3, wn = wid >> 2;
    int row0 = bx * 128;

    float acc[2][8][4];
    #pragma unroll
    for (int i = 0; i < 2; i++)
        #pragma unroll
        for (int j = 0; j < 8; j++)
            #pragma unroll
            for (int q = 0; q < 4; q++) acc[i][j][q] = 0.f;

    const int T = DUAL ? 16 : 8;
    int sr = tid >> 1, sp = tid & 1;
    uint32_t soff = swz(sr, sp);
    int sgr = row0 + sr;
    bool svalid = sgr < n;
    size_t s_asrc = (size_t)(svalid ? sgr : 0) * 128 + sp * 8;
    size_t s_wsrc = (size_t)sr * 128 + sp * 8;

    auto do_stage = [&](int c) {
        int pass = DUAL ? (c >> 3) : 0;
        int kc = c & 7, s = c & 1;
        const __half* A = g_Pf[pass ? INA2 : INA1];
        int wi = pass ? W2I : W1I;
        uint32_t b = sbase + s * 12288;
        size_t ka = s_asrc + kc * 16, kw = s_wsrc + kc * 16;
        cpasync16(b + soff,        A + ka, svalid ? 16 : 0);
        cpasync16(b + 4096 + soff, g_wimg[wi][0] + kw, 16);
        cpasync16(b + 8192 + soff, g_wimg[wi][1] + kw, 16);
    };

    do_stage(0);
    cp_commit();

    for (int c = 0; c < T; c++) {
        if (c + 1 < T) {
            do_stage(c + 1);
            cp_commit();
            cp_wait<1>();
        } else {
            cp_wait<0>();
        }
        __syncthreads();

        uint32_t b0 = sbase + (c & 1) * 12288;
        uint32_t a[2][4];
        #pragma unroll
        for (int mi = 0; mi < 2; mi++) {
            int row = wm * 32 + mi * 16 + (lane & 15);
            ldsm4(a[mi], b0 + swz(row, lane >> 4));
        }
        #pragma unroll
        for (int term = 0; term < 2; term++) {
            uint32_t wb = b0 + 4096 + term * 4096;
            uint32_t bf[8][2];
            #pragma unroll
            for (int q = 0; q < 4; q++) {
                int rown = wn * 64 + q * 16 + ((lane >> 4) << 3) + (lane & 7);
                uint32_t r4[4];
                ldsm4(r4, wb + swz(rown, (lane >> 3) & 1));
                bf[q * 2 + 0][0] = r4[0]; bf[q * 2 + 0][1] = r4[1];
                bf[q * 2 + 1][0] = r4[2]; bf[q * 2 + 1][1] = r4[3];
            }
            #pragma unroll
            for (int mi = 0; mi < 2; mi++)
                #pragma unroll
                for (int nj = 0; nj < 8; nj++)
                    mma_f16(acc[mi][nj], a[mi], bf[nj]);
        }
        __syncthreads();
    }

    // epilogue (descale by WINV, then bias)
    int rbase = row0 + wm * 32 + (lane >> 2);
    int cbase = wn * 64 + (lane & 3) * 2;
    #pragma unroll
    for (int mi = 0; mi < 2; mi++) {
        #pragma unroll
        for (int half = 0; half < 2; half++) {
            int gr = rbase + mi * 16 + half * 8;
            if (gr >= n) continue;
            float s = (BSEL == 3) ? (float)(g_cnt[gr] + 1) : 0.f;
            #pragma unroll
            for (int nj = 0; nj < 8; nj++) {
                int col = cbase + nj * 8;
                float v0, v1;
                if (BSEL == 3) {
                    v0 = acc[mi][nj][half * 2 + 0] * WINV + s * g_c1[col]     + g_c0[col];
                    v1 = acc[mi][nj][half * 2 + 1] * WINV + s * g_c1[col + 1] + g_c0[col + 1];
                } else {
                    v0 = acc[mi][nj][half * 2 + 0] * WINV + bias_param[col];
                    v1 = acc[mi][nj][half * 2 + 1] * WINV + bias_param[col + 1];
                }
                if (RELU) { v0 = fmaxf(v0, 0.f); v1 = fmaxf(v1, 0.f); }
                if (OUTF32) {
                    *(float2*)&outp[(size_t)gr * 128 + col] = make_float2(v0, v1);
                } else if (OUTHA) {
                    // h into interleaved HA: halves index = gr*256 + (col>>2)*8 + (col&3)
                    __half2 hh = __floats2half2_rn(v0, v1);
                    size_t hidx = (size_t)gr * 256 + (size_t)(col >> 2) * 8 + (col & 3);
                    *(__half2*)&g_HA[hidx] = hh;
                } else {
                    __half2 hh = __floats2half2_rn(v0, v1);
                    *(__half2*)&g_Pf[OUTI][(size_t)gr * 128 + col] = hh;
                }
            }
        }
    }
}

// layer-1 GCN: h = relu(P0 @ gcn_w1 + b1) -> HA panel (h-slots)
__global__ void __launch_bounds__(256, 2) k_tgemm_l1(const float* __restrict__ b1,
                                                     float* __restrict__ outp, int n) {
    __shared__ __align__(1024) unsigned char sbuf[2 * 12288];
    tgemm_body<true, false, 0, 0, 0, 0, 0, 0, false, true>(blockIdx.x, b1, outp, n, smem_u32(sbuf));
}
// layer-2 fused head: out = P0@Wg + P3@Wn + (cnt+1)*c1 + c0   (fp32 out)
__global__ void __launch_bounds__(256, 2) k_tgemm_l2(float* __restrict__ outp, int n) {
    __shared__ __align__(1024) unsigned char sbuf[2 * 12288];
    tgemm_body<false, true, 0, 3, 0, 1, 2, 3, true, false>(blockIdx.x, outp, outp, n, smem_u32(sbuf));
}

// ---------------- launch ----------------
extern "C" void kernel_launch(void* const* d_in, const int* in_sizes, int n_in,
                              void* d_out, int out_size) {
    const float* X      = (const float*)d_in[0];
    const int*   ei     = (const int*)d_in[1];
    const float* gcn_w1 = (const float*)d_in[2];
    const float* gcn_b1 = (const float*)d_in[3];
    const float* gcn_w2 = (const float*)d_in[4];
    const float* gcn_b2 = (const float*)d_in[5];
    const float* gin_w1 = (const float*)d_in[6];
    const float* gin_b1 = (const float*)d_in[7];
    const float* gin_w2 = (const float*)d_in[8];
    const float* gin_b2 = (const float*)d_in[9];
    const float* lin_w  = (const float*)d_in[10];
    const float* lin_b  = (const float*)d_in[11];
    const float* fc_w   = (const float*)d_in[12];
    const float* fc_b   = (const float*)d_in[13];
    float*       out    = (float*)d_out;

    int N = in_sizes[0] / DD;
    int E = in_sizes[1] / 2;

    int nb = (N + 1023) / 1024;
    int gN = (N + 255) / 256;
    int gE = (E + 255) / 256;
    int gW = (N + 7) / 8;
    int gG = (N + 127) / 128;

    // CSR build
    k_zero_cnt<<<gN, 256>>>(N);
    k_hist<<<gE, 256>>>(ei, E, N);
    k_scan1<<<nb, 1024>>>(N);
    k_scan2<<<1, 256>>>(nb);
    k_scan3<<<gN, 256>>>(N, E);
    k_fill<<<gE, 256>>>(ei, E, N);

    // weight folding + fp16 images
    k_prepA<<<2 * DD + 1, DD>>>(lin_w, lin_b, fc_w, fc_b, gin_w1, gin_w2);
    k_prepB<<<3 * DD + 1, DD>>>(gcn_w2, gin_w2, gcn_b2, gin_b2);
    k_c1<<<1, DD>>>(gin_b1);
    k_wprep<<<dim3(64, 3), 256>>>(gcn_w1);

    // layer 1
    k_agg1<<<gW, 256>>>(X, N);
    k_tgemm_l1<<<gG, 256>>>(gcn_b1, out, N);

    // layer 2
    k_agg2<<<gW, 256>>>(N);
    k_tgemm_l2<<<gG, 256>>>(out, N);
}

// round 16
// speedup vs baseline: 1.6291x; 1.0593x over previous
#include <cuda_runtime.h>
#include <cuda_fp16.h>
#include <cstdint>

#define DD 128
#define NMAX 100000
#define EMAX 1600000
#define WSCALE 256.0f
#define WINV   (1.0f / 256.0f)

// ---------------- static scratch ----------------
__device__ int   g_cnt[NMAX];
__device__ int   g_rowptr[NMAX + 1];
__device__ int   g_col[EMAX];
__device__ __align__(16) float g_dinv[NMAX];
__device__ int   g_blocksums[256];
__device__ __align__(16) float g_M[DD * DD];     // lin@fc
__device__ __align__(16) float g_P[DD * DD];     // gin_w1 @ gin_w2
__device__ __align__(16) float g_Wg[DD * DD];    // gcn_w2 @ M
__device__ __align__(16) float g_Wn2[DD * DD];   // gin_w2 @ M
__device__ __align__(16) float g_Wn[DD * DD];    // P @ M
__device__ __align__(16) float g_c0a[DD];
__device__ __align__(16) float g_c0[DD];
__device__ __align__(16) float g_c1[DD];
// fp16 weight images [matrix][hi/lo], [n][k] layout, pre-scaled by WSCALE
// 0=gcn_w1, 1=Wg, 2=Wn
__device__ __align__(16) __half g_wimg[3][2][16384];
// fp16 panels: 0=aggW(X)/aggW(h), 1=A1=X+aggU(X), 2=h, 3=A2
__device__ __align__(16) __half g_Pf[4][(size_t)NMAX * DD];

// ---------------- PTX helpers ----------------
__device__ __forceinline__ uint32_t smem_u32(const void* p) {
    uint32_t a;
    asm("{ .reg .u64 t; cvta.to.shared.u64 t, %1; cvt.u32.u64 %0, t; }" : "=r"(a) : "l"(p));
    return a;
}
__device__ __forceinline__ void ldsm4(uint32_t* r, uint32_t addr) {
    asm volatile("ldmatrix.sync.aligned.m8n8.x4.shared.b16 {%0,%1,%2,%3}, [%4];"
                 : "=r"(r[0]), "=r"(r[1]), "=r"(r[2]), "=r"(r[3]) : "r"(addr));
}
__device__ __forceinline__ void mma_f16(float* c, const uint32_t* a, const uint32_t* b) {
    asm volatile("mma.sync.aligned.m16n8k16.row.col.f32.f16.f16.f32 "
                 "{%0,%1,%2,%3}, {%4,%5,%6,%7}, {%8,%9}, {%0,%1,%2,%3};"
                 : "+f"(c[0]), "+f"(c[1]), "+f"(c[2]), "+f"(c[3])
                 : "r"(a[0]), "r"(a[1]), "r"(a[2]), "r"(a[3]), "r"(b[0]), "r"(b[1]));
}
__device__ __forceinline__ void cpasync16(uint32_t dst, const void* src, int szbytes) {
    asm volatile("cp.async.cg.shared.global [%0], [%1], 16, %2;"
                 :: "r"(dst), "l"(src), "r"(szbytes) : "memory");
}
__device__ __forceinline__ void cp_commit() { asm volatile("cp.async.commit_group;" ::: "memory"); }
template <int N> __device__ __forceinline__ void cp_wait() {
    asm volatile("cp.async.wait_group %0;" :: "n"(N) : "memory");
}
// conflict-free chunk16 tile: row r (0..127) of 16 fp16 = 2x16B pieces, stride 32B
__device__ __forceinline__ uint32_t swz(int r, int p) {
    return (uint32_t)(r * 32 + ((p ^ (r & 1) ^ ((r >> 2) & 1)) << 4));
}
__device__ __forceinline__ uint32_t h2u(__half2 h) { return *(uint32_t*)&h; }
__device__ __forceinline__ void storeh4(__half* p, size_t idx, float4 v) {
    __half2 a = __floats2half2_rn(v.x, v.y);
    __half2 b = __floats2half2_rn(v.z, v.w);
    *(uint2*)(p + idx) = make_uint2(h2u(a), h2u(b));
}
__device__ __forceinline__ float4 loadh4(const __half* p, size_t idx) {
    uint2 u = *(const uint2*)(p + idx);
    float2 fa = __half22float2(*(__half2*)&u.x);
    float2 fb = __half22float2(*(__half2*)&u.y);
    return make_float4(fa.x, fa.y, fb.x, fb.y);
}

// ---------------- merged prep/CSR kernels ----------------
// m1: blocks [0,gN) zero_cnt; [gN, gN+2*DD+1) prepA
__global__ void k_m1(int n, int gN,
                     const float* __restrict__ lin_w, const float* __restrict__ lin_b,
                     const float* __restrict__ fc_w, const float* __restrict__ fc_b,
                     const float* __restrict__ gin_w1, const float* __restrict__ gin_w2) {
    int b = blockIdx.x;
    if (b < gN) {
        int i = b * 256 + threadIdx.x;
        if (i < n) g_cnt[i] = 0;
        return;
    }
    int bb = b - gN;
    int c = threadIdx.x;
    if (c >= DD) return;
    if (bb < DD) {
        float a = 0.f;
        #pragma unroll 8
        for (int k = 0; k < DD; k++) a += lin_w[bb * DD + k] * fc_w[k * DD + c];
        g_M[bb * DD + c] = a;
    } else if (bb < 2 * DD) {
        int r = bb - DD;
        float a = 0.f;
        #pragma unroll 8
        for (int k = 0; k < DD; k++) a += gin_w1[r * DD + k] * gin_w2[k * DD + c];
        g_P[r * DD + c] = a;
    } else {
        float a = 0.f;
        #pragma unroll 8
        for (int k = 0; k < DD; k++) a += lin_b[k] * fc_w[k * DD + c];
        g_c0a[c] = 2.f * a + fc_b[c];
    }
}
// m2: blocks [0,gE) hist; [gE, gE+3*DD+1) prepB
__global__ void k_m2(const int* __restrict__ ei, int E, int n, int gE,
                     const float* __restrict__ gcn_w2, const float* __restrict__ gin_w2,
                     const float* __restrict__ gcn_b2, const float* __restrict__ gin_b2) {
    int b = blockIdx.x;
    if (b < gE) {
        int e = b * 256 + threadIdx.x;
        if (e < E) {
            int d = ei[E + e];
            if (d >= 0 && d < n) atomicAdd(&g_cnt[d], 1);
        }
        return;
    }
    int bb = b - gE;
    int c = threadIdx.x;
    if (c >= DD) return;
    if (bb < DD) {
        float a = 0.f;
        #pragma unroll 8
        for (int k = 0; k < DD; k++) a += gcn_w2[bb * DD + k] * g_M[k * DD + c];
        g_Wg[bb * DD + c] = a;
    } else if (bb < 2 * DD) {
        int r = bb - DD;
        float a = 0.f;
        #pragma unroll 8
        for (int k = 0; k < DD; k++) a += gin_w2[r * DD + k] * g_M[k * DD + c];
        g_Wn2[r * DD + c] = a;
    } else if (bb < 3 * DD) {
        int r = bb - 2 * DD;
        float a = 0.f;
        #pragma unroll 8
        for (int k = 0; k < DD; k++) a += g_P[r * DD + k] * g_M[k * DD + c];
        g_Wn[r * DD + c] = a;
    } else {
        float a = 0.f;
        #pragma unroll 8
        for (int k = 0; k < DD; k++)
            a += (gcn_b2[k] + gin_b2[k]) * g_M[k * DD + c];
        g_c0[c] = a + g_c0a[c];
    }
}
__global__ void k_scan1(int n) {
    __shared__ int s[1024];
    int i = blockIdx.x * 1024 + threadIdx.x;
    int v = (i < n) ? g_cnt[i] : 0;
    s[threadIdx.x] = v;
    __syncthreads();
    for (int off = 1; off < 1024; off <<= 1) {
        int t = (threadIdx.x >= off) ? s[threadIdx.x - off] : 0;
        __syncthreads();
        s[threadIdx.x] += t;
        __syncthreads();
    }
    if (i < n) g_rowptr[i] = s[threadIdx.x] - v;   // exclusive within block
    if (threadIdx.x == 1023) g_blocksums[blockIdx.x] = s[1023];  // block total
}
// m3: blocks [0,gN) scan3 (inline blocksum prefix); [gN, gN+192) wprep; [gN+192] c1
__global__ void k_m3(int n, int E, int gN,
                     const float* __restrict__ gcn_w1, const float* __restrict__ gin_b1) {
    int b = blockIdx.x;
    if (b < gN) {
        int i = b * 256 + threadIdx.x;
        if (i < n) {
            int nb = i >> 10;
            int pref = 0;
            for (int q = 0; q < nb; q++) pref += g_blocksums[q];
            g_rowptr[i] += pref;
            g_dinv[i] = rsqrtf((float)g_cnt[i] + 1.0f);
            g_cnt[i] = 0;
        }
        if (i == 0) g_rowptr[n] = E;
        return;
    }
    int bb = b - gN;
    if (bb < 192) {
        int mat = bb >> 6;
        int i = (bb & 63) * 256 + threadIdx.x;
        if (i >= 16384) return;
        int k = i >> 7, nn = i & 127;
        const float* W = (mat == 0) ? gcn_w1 : (mat == 1) ? g_Wg : g_Wn;
        float x = W[k * 128 + nn] * WSCALE;
        __half hi = __float2half_rn(x);
        __half lo = __float2half_rn(x - __half2float(hi));
        g_wimg[mat][0][nn * 128 + k] = hi;
        g_wimg[mat][1][nn * 128 + k] = lo;
    } else {
        int c = threadIdx.x;
        if (c < DD) {
            float a = 0.f;
            #pragma unroll 8
            for (int k = 0; k < DD; k++) a += gin_b1[k] * g_Wn2[k * DD + c];
            g_c1[c] = a;
        }
    }
}
__global__ void k_fill(const int* __restrict__ ei, int E, int n) {
    int e = blockIdx.x * blockDim.x + threadIdx.x;
    if (e < E) {
        int s = ei[e];
        int d = ei[E + e];
        if (s >= 0 && s < n && d >= 0 && d < n) {
            int pos = g_rowptr[d] + atomicAdd(&g_cnt[d], 1);
            g_col[pos] = s;
        }
    }
}
// after k_fill, g_cnt[i] == incoming degree again (used by l2 epilogue)

// ---------------- aggregation (warp per node; exact R12 versions) ----------------
// pass1 (fp32 X): P0 = aggW(X)+self, P1 = A1 = X + aggU(X)
__global__ void k_agg1(const float* __restrict__ X, int n) {
    int w = (blockIdx.x * blockDim.x + threadIdx.x) >> 5;
    if (w >= n) return;
    int lane = threadIdx.x & 31;
    const float4* Xv = (const float4*)X;
    int e = g_rowptr[w], end = g_rowptr[w + 1];
    float4 aw = make_float4(0, 0, 0, 0), au = make_float4(0, 0, 0, 0);
    for (; e + 4 <= end; e += 4) {
        int j0 = g_col[e], j1 = g_col[e + 1], j2 = g_col[e + 2], j3 = g_col[e + 3];
        float d0 = g_dinv[j0], d1 = g_dinv[j1], d2 = g_dinv[j2], d3 = g_dinv[j3];
        float4 v0 = Xv[(size_t)j0 * 32 + lane];
        float4 v1 = Xv[(size_t)j1 * 32 + lane];
        float4 v2 = Xv[(size_t)j2 * 32 + lane];
        float4 v3 = Xv[(size_t)j3 * 32 + lane];
        aw.x += d0 * v0.x + d1 * v1.x + d2 * v2.x + d3 * v3.x;
        aw.y += d0 * v0.y + d1 * v1.y + d2 * v2.y + d3 * v3.y;
        aw.z += d0 * v0.z + d1 * v1.z + d2 * v2.z + d3 * v3.z;
        aw.w += d0 * v0.w + d1 * v1.w + d2 * v2.w + d3 * v3.w;
        au.x += v0.x + v1.x + v2.x + v3.x;
        au.y += v0.y + v1.y + v2.y + v3.y;
        au.z += v0.z + v1.z + v2.z + v3.z;
        au.w += v0.w + v1.w + v2.w + v3.w;
    }
    for (; e < end; e++) {
        int j = g_col[e];
        float dj = g_dinv[j];
        float4 v = Xv[(size_t)j * 32 + lane];
        aw.x += dj * v.x; aw.y += dj * v.y; aw.z += dj * v.z; aw.w += dj * v.w;
        au.x += v.x;      au.y += v.y;      au.z += v.z;      au.w += v.w;
    }
    float di = g_dinv[w], dii = di * di;
    float4 xi = Xv[(size_t)w * 32 + lane];
    float4 ow, ou;
    ow.x = di * aw.x + dii * xi.x; ow.y = di * aw.y + dii * xi.y;
    ow.z = di * aw.z + dii * xi.z; ow.w = di * aw.w + dii * xi.w;
    ou.x = au.x + xi.x; ou.y = au.y + xi.y; ou.z = au.z + xi.z; ou.w = au.w + xi.w;
    size_t idx = (size_t)w * 128 + lane * 4;
    storeh4(g_Pf[0], idx, ow);
    storeh4(g_Pf[1], idx, ou);
}
// pass2: P0 = aggW(P2=h)+self, P3 = A2 = P1 + aggU(P1)
__global__ void k_agg2(int n) {
    int w = (blockIdx.x * blockDim.x + threadIdx.x) >> 5;
    if (w >= n) return;
    int lane = threadIdx.x & 31;
    int e = g_rowptr[w], end = g_rowptr[w + 1];
    float4 aw = make_float4(0, 0, 0, 0), au = make_float4(0, 0, 0, 0);
    for (; e + 4 <= end; e += 4) {
        int j0 = g_col[e], j1 = g_col[e + 1], j2 = g_col[e + 2], j3 = g_col[e + 3];
        float d0 = g_dinv[j0], d1 = g_dinv[j1], d2 = g_dinv[j2], d3 = g_dinv[j3];
        size_t i0 = (size_t)j0 * 128 + lane * 4, i1 = (size_t)j1 * 128 + lane * 4;
        size_t i2 = (size_t)j2 * 128 + lane * 4, i3 = (size_t)j3 * 128 + lane * 4;
        float4 h0 = loadh4(g_Pf[2], i0);
        float4 h1 = loadh4(g_Pf[2], i1);
        float4 h2 = loadh4(g_Pf[2], i2);
        float4 h3 = loadh4(g_Pf[2], i3);
        float4 a0 = loadh4(g_Pf[1], i0);
        float4 a1 = loadh4(g_Pf[1], i1);
        float4 a2 = loadh4(g_Pf[1], i2);
        float4 a3 = loadh4(g_Pf[1], i3);
        aw.x += d0 * h0.x + d1 * h1.x + d2 * h2.x + d3 * h3.x;
        aw.y += d0 * h0.y + d1 * h1.y + d2 * h2.y + d3 * h3.y;
        aw.z += d0 * h0.z + d1 * h1.z + d2 * h2.z + d3 * h3.z;
        aw.w += d0 * h0.w + d1 * h1.w + d2 * h2.w + d3 * h3.w;
        au.x += a0.x + a1.x + a2.x + a3.x;
        au.y += a0.y + a1.y + a2.y + a3.y;
        au.z += a0.z + a1.z + a2.z + a3.z;
        au.w += a0.w + a1.w + a2.w + a3.w;
    }
    for (; e < end; e++) {
        int j = g_col[e];
        float dj = g_dinv[j];
        size_t i0 = (size_t)j * 128 + lane * 4;
        float4 hv = loadh4(g_Pf[2], i0);
        float4 av = loadh4(g_Pf[1], i0);
        aw.x += dj * hv.x; aw.y += dj * hv.y; aw.z += dj * hv.z; aw.w += dj * hv.w;
        au.x += av.x;      au.y += av.y;      au.z += av.z;      au.w += av.w;
    }
    float di = g_dinv[w], dii = di * di;
    size_t iw = (size_t)w * 128 + lane * 4;
    float4 hi = loadh4(g_Pf[2], iw);
    float4 ai = loadh4(g_Pf[1], iw);
    float4 ow, ou;
    ow.x = di * aw.x + dii * hi.x; ow.y = di * aw.y + dii * hi.y;
    ow.z = di * aw.z + dii * hi.z; ow.w = di * aw.w + dii * hi.w;
    ou.x = au.x + ai.x; ou.y = au.y + ai.y; ou.z = au.z + ai.z; ou.w = au.w + ai.w;
    storeh4(g_Pf[0], iw, ow);
    storeh4(g_Pf[3], iw, ou);
}

// ---------------- pipelined fp16 warp-mma GEMM (exact R12 version) ----------------
template <bool RELU, bool DUAL, int INA1, int INA2, int OUTI, int W1I, int W2I,
          int BSEL, bool OUTF32>
__device__ __forceinline__ void tgemm_body(int bx, const float* bias_param,
                                           float* outp, int n, uint32_t sbase) {
    int tid = threadIdx.x, lane = tid & 31, wid = tid >> 5;
    int wm = wid & 3, wn = wid >> 2;
    int row0 = bx * 128;

    float acc[2][8][4];
    #pragma unroll
    for (int i = 0; i < 2; i++)
        #pragma unroll
        for (int j = 0; j < 8; j++)
            #pragma unroll
            for (int q = 0; q < 4; q++) acc[i][j][q] = 0.f;

    const int T = DUAL ? 16 : 8;
    int sr = tid >> 1, sp = tid & 1;
    uint32_t soff = swz(sr, sp);
    int sgr = row0 + sr;
    bool svalid = sgr < n;
    size_t s_asrc = (size_t)(svalid ? sgr : 0) * 128 + sp * 8;
    size_t s_wsrc = (size_t)sr * 128 + sp * 8;

    auto do_stage = [&](int c) {
        int pass = DUAL ? (c >> 3) : 0;
        int kc = c & 7, s = c & 1;
        const __half* A = g_Pf[pass ? INA2 : INA1];
        int wi = pass ? W2I : W1I;
        uint32_t b = sbase + s * 12288;
        size_t ka = s_asrc + kc * 16, kw = s_wsrc + kc * 16;
        cpasync16(b + soff,        A + ka, svalid ? 16 : 0);
        cpasync16(b + 4096 + soff, g_wimg[wi][0] + kw, 16);
        cpasync16(b + 8192 + soff, g_wimg[wi][1] + kw, 16);
    };

    do_stage(0);
    cp_commit();

    for (int c = 0; c < T; c++) {
        if (c + 1 < T) {
            do_stage(c + 1);
            cp_commit();
            cp_wait<1>();
        } else {
            cp_wait<0>();
        }
        __syncthreads();

        uint32_t b0 = sbase + (c & 1) * 12288;
        uint32_t a[2][4];
        #pragma unroll
        for (int mi = 0; mi < 2; mi++) {
            int row = wm * 32 + mi * 16 + (lane & 15);
            ldsm4(a[mi], b0 + swz(row, lane >> 4));
        }
        #pragma unroll
        for (int term = 0; term < 2; term++) {
            uint32_t wb = b0 + 4096 + term * 4096;
            uint32_t bf[8][2];
            #pragma unroll
            for (int q = 0; q < 4; q++) {
                int rown = wn * 64 + q * 16 + ((lane >> 4) << 3) + (lane & 7);
                uint32_t r4[4];
                ldsm4(r4, wb + swz(rown, (lane >> 3) & 1));
                bf[q * 2 + 0][0] = r4[0]; bf[q * 2 + 0][1] = r4[1];
                bf[q * 2 + 1][0] = r4[2]; bf[q * 2 + 1][1] = r4[3];
            }
            #pragma unroll
            for (int mi = 0; mi < 2; mi++)
                #pragma unroll
                for (int nj = 0; nj < 8; nj++)
                    mma_f16(acc[mi][nj], a[mi], bf[nj]);
        }
        __syncthreads();
    }

    // epilogue (descale by WINV, then bias)
    int rbase = row0 + wm * 32 + (lane >> 2);
    int cbase = wn * 64 + (lane & 3) * 2;
    #pragma unroll
    for (int mi = 0; mi < 2; mi++) {
        #pragma unroll
        for (int half = 0; half < 2; half++) {
            int gr = rbase + mi * 16 + half * 8;
            if (gr >= n) continue;
            float s = (BSEL == 3) ? (float)(g_cnt[gr] + 1) : 0.f;
            #pragma unroll
            for (int nj = 0; nj < 8; nj++) {
                int col = cbase + nj * 8;
                float v0, v1;
                if (BSEL == 3) {
                    v0 = acc[mi][nj][half * 2 + 0] * WINV + s * g_c1[col]     + g_c0[col];
                    v1 = acc[mi][nj][half * 2 + 1] * WINV + s * g_c1[col + 1] + g_c0[col + 1];
                } else {
                    v0 = acc[mi][nj][half * 2 + 0] * WINV + bias_param[col];
                    v1 = acc[mi][nj][half * 2 + 1] * WINV + bias_param[col + 1];
                }
                if (RELU) { v0 = fmaxf(v0, 0.f); v1 = fmaxf(v1, 0.f); }
                if (OUTF32) {
                    *(float2*)&outp[(size_t)gr * 128 + col] = make_float2(v0, v1);
                } else {
                    __half2 hh = __floats2half2_rn(v0, v1);
                    *(__half2*)&g_Pf[OUTI][(size_t)gr * 128 + col] = hh;
                }
            }
        }
    }
}

// layer-1 GCN: h = relu(P0 @ gcn_w1 + b1) -> P2 fp16
__global__ void __launch_bounds__(256, 2) k_tgemm_l1(const float* __restrict__ b1,
                                                     float* __restrict__ outp, int n) {
    __shared__ __align__(1024) unsigned char sbuf[2 * 12288];
    tgemm_body<true, false, 0, 0, 2, 0, 0, 0, false>(blockIdx.x, b1, outp, n, smem_u32(sbuf));
}
// layer-2 fused head: out = P0@Wg + P3@Wn + (cnt+1)*c1 + c0   (fp32 out)
__global__ void __launch_bounds__(256, 2) k_tgemm_l2(float* __restrict__ outp, int n) {
    __shared__ __align__(1024) unsigned char sbuf[2 * 12288];
    tgemm_body<false, true, 0, 3, 0, 1, 2, 3, true>(blockIdx.x, outp, outp, n, smem_u32(sbuf));
}

// ---------------- launch ----------------
extern "C" void kernel_launch(void* const* d_in, const int* in_sizes, int n_in,
                              void* d_out, int out_size) {
    const float* X      = (const float*)d_in[0];
    const int*   ei     = (const int*)d_in[1];
    const float* gcn_w1 = (const float*)d_in[2];
    const float* gcn_b1 = (const float*)d_in[3];
    const float* gcn_w2 = (const float*)d_in[4];
    const float* gcn_b2 = (const float*)d_in[5];
    const float* gin_w1 = (const float*)d_in[6];
    const float* gin_b1 = (const float*)d_in[7];
    const float* gin_w2 = (const float*)d_in[8];
    const float* gin_b2 = (const float*)d_in[9];
    const float* lin_w  = (const float*)d_in[10];
    const float* lin_b  = (const float*)d_in[11];
    const float* fc_w   = (const float*)d_in[12];
    const float* fc_b   = (const float*)d_in[13];
    float*       out    = (float*)d_out;

    int N = in_sizes[0] / DD;
    int E = in_sizes[1] / 2;

    int nb = (N + 1023) / 1024;
    int gN = (N + 255) / 256;
    int gE = (E + 255) / 256;
    int gW = (N + 7) / 8;
    int gG = (N + 127) / 128;

    // merged CSR + weight-folding chain (8 launches total)
    k_m1<<<gN + 2 * DD + 1, 256>>>(N, gN, lin_w, lin_b, fc_w, fc_b, gin_w1, gin_w2);
    k_m2<<<gE + 3 * DD + 1, 256>>>(ei, E, N, gE, gcn_w2, gin_w2, gcn_b2, gin_b2);
    k_scan1<<<nb, 1024>>>(N);
    k_m3<<<gN + 193, 256>>>(N, E, gN, gcn_w1, gin_b1);
    k_fill<<<gE, 256>>>(ei, E, N);

    // layer 1
    k_agg1<<<gW, 256>>>(X, N);
    k_tgemm_l1<<<gG, 256>>>(gcn_b1, out, N);

    // layer 2
    k_agg2<<<gW, 256>>>(N);
    k_tgemm_l2<<<gG, 256>>>(out, N);
}

// round 17
// speedup vs baseline: 1.6345x; 1.0033x over previous
#include <cuda_runtime.h>
#include <cuda_fp16.h>
#include <cstdint>

#define DD 128
#define NMAX 100000
#define EMAX 1600000
#define WSCALE 256.0f
#define WINV   (1.0f / 256.0f)

// ---------------- static scratch ----------------
__device__ int   g_cnt[NMAX];
__device__ int   g_rowptr[NMAX + 1];
__device__ int   g_col[EMAX];
__device__ __align__(16) float g_dinv[NMAX];
__device__ int   g_blocksums[256];
__device__ __align__(16) float g_M[DD * DD];     // lin@fc
__device__ __align__(16) float g_P[DD * DD];     // gin_w1 @ gin_w2
__device__ __align__(16) float g_Wg[DD * DD];    // gcn_w2 @ M
__device__ __align__(16) float g_Wn2[DD * DD];   // gin_w2 @ M
__device__ __align__(16) float g_Wn[DD * DD];    // P @ M
__device__ __align__(16) float g_c0a[DD];
__device__ __align__(16) float g_c0[DD];
__device__ __align__(16) float g_c1[DD];
// fp16 weight images [matrix][hi/lo], [n][k] layout, pre-scaled by WSCALE
// 0=gcn_w1, 1=Wg, 2=Wn
__device__ __align__(16) __half g_wimg[3][2][16384];
// fp16 panels: 0=aggW(X)/aggW(h), 1=A1=X+aggU(X), 2=h, 3=A2
__device__ __align__(16) __half g_Pf[4][(size_t)NMAX * DD];

// ---------------- PTX helpers ----------------
__device__ __forceinline__ uint32_t smem_u32(const void* p) {
    uint32_t a;
    asm("{ .reg .u64 t; cvta.to.shared.u64 t, %1; cvt.u32.u64 %0, t; }" : "=r"(a) : "l"(p));
    return a;
}
__device__ __forceinline__ void ldsm4(uint32_t* r, uint32_t addr) {
    asm volatile("ldmatrix.sync.aligned.m8n8.x4.shared.b16 {%0,%1,%2,%3}, [%4];"
                 : "=r"(r[0]), "=r"(r[1]), "=r"(r[2]), "=r"(r[3]) : "r"(addr));
}
__device__ __forceinline__ void mma_f16(float* c, const uint32_t* a, const uint32_t* b) {
    asm volatile("mma.sync.aligned.m16n8k16.row.col.f32.f16.f16.f32 "
                 "{%0,%1,%2,%3}, {%4,%5,%6,%7}, {%8,%9}, {%0,%1,%2,%3};"
                 : "+f"(c[0]), "+f"(c[1]), "+f"(c[2]), "+f"(c[3])
                 : "r"(a[0]), "r"(a[1]), "r"(a[2]), "r"(a[3]), "r"(b[0]), "r"(b[1]));
}
__device__ __forceinline__ void cpasync16(uint32_t dst, const void* src, int szbytes) {
    asm volatile("cp.async.cg.shared.global [%0], [%1], 16, %2;"
                 :: "r"(dst), "l"(src), "r"(szbytes) : "memory");
}
__device__ __forceinline__ void cp_commit() { asm volatile("cp.async.commit_group;" ::: "memory"); }
template <int N> __device__ __forceinline__ void cp_wait() {
    asm volatile("cp.async.wait_group %0;" :: "n"(N) : "memory");
}
// conflict-free chunk16 tile: row r (0..127) of 16 fp16 = 2x16B pieces, stride 32B
__device__ __forceinline__ uint32_t swz(int r, int p) {
    return (uint32_t)(r * 32 + ((p ^ (r & 1) ^ ((r >> 2) & 1)) << 4));
}
__device__ __forceinline__ uint32_t h2u(__half2 h) { return *(uint32_t*)&h; }
__device__ __forceinline__ void storeh4(__half* p, size_t idx, float4 v) {
    __half2 a = __floats2half2_rn(v.x, v.y);
    __half2 b = __floats2half2_rn(v.z, v.w);
    *(uint2*)(p + idx) = make_uint2(h2u(a), h2u(b));
}
__device__ __forceinline__ float4 loadh4(const __half* p, size_t idx) {
    uint2 u = *(const uint2*)(p + idx);
    float2 fa = __half22float2(*(__half2*)&u.x);
    float2 fb = __half22float2(*(__half2*)&u.y);
    return make_float4(fa.x, fa.y, fb.x, fb.y);
}

// ---------------- merged prep/CSR kernels ----------------
// m1: blocks [0,gN) zero_cnt; [gN, gN+2*DD+1) prepA
__global__ void k_m1(int n, int gN,
                     const float* __restrict__ lin_w, const float* __restrict__ lin_b,
                     const float* __restrict__ fc_w, const float* __restrict__ fc_b,
                     const float* __restrict__ gin_w1, const float* __restrict__ gin_w2) {
    int b = blockIdx.x;
    if (b < gN) {
        int i = b * 256 + threadIdx.x;
        if (i < n) g_cnt[i] = 0;
        return;
    }
    int bb = b - gN;
    int c = threadIdx.x;
    if (c >= DD) return;
    if (bb < DD) {
        float a = 0.f;
        #pragma unroll 8
        for (int k = 0; k < DD; k++) a += lin_w[bb * DD + k] * fc_w[k * DD + c];
        g_M[bb * DD + c] = a;
    } else if (bb < 2 * DD) {
        int r = bb - DD;
        float a = 0.f;
        #pragma unroll 8
        for (int k = 0; k < DD; k++) a += gin_w1[r * DD + k] * gin_w2[k * DD + c];
        g_P[r * DD + c] = a;
    } else {
        float a = 0.f;
        #pragma unroll 8
        for (int k = 0; k < DD; k++) a += lin_b[k] * fc_w[k * DD + c];
        g_c0a[c] = 2.f * a + fc_b[c];
    }
}
// m2: blocks [0,gE) hist; [gE, gE+3*DD+1) prepB
__global__ void k_m2(const int* __restrict__ ei, int E, int n, int gE,
                     const float* __restrict__ gcn_w2, const float* __restrict__ gin_w2,
                     const float* __restrict__ gcn_b2, const float* __restrict__ gin_b2) {
    int b = blockIdx.x;
    if (b < gE) {
        int e = b * 256 + threadIdx.x;
        if (e < E) {
            int d = ei[E + e];
            if (d >= 0 && d < n) atomicAdd(&g_cnt[d], 1);
        }
        return;
    }
    int bb = b - gE;
    int c = threadIdx.x;
    if (c >= DD) return;
    if (bb < DD) {
        float a = 0.f;
        #pragma unroll 8
        for (int k = 0; k < DD; k++) a += gcn_w2[bb * DD + k] * g_M[k * DD + c];
        g_Wg[bb * DD + c] = a;
    } else if (bb < 2 * DD) {
        int r = bb - DD;
        float a = 0.f;
        #pragma unroll 8
        for (int k = 0; k < DD; k++) a += gin_w2[r * DD + k] * g_M[k * DD + c];
        g_Wn2[r * DD + c] = a;
    } else if (bb < 3 * DD) {
        int r = bb - 2 * DD;
        float a = 0.f;
        #pragma unroll 8
        for (int k = 0; k < DD; k++) a += g_P[r * DD + k] * g_M[k * DD + c];
        g_Wn[r * DD + c] = a;
    } else {
        float a = 0.f;
        #pragma unroll 8
        for (int k = 0; k < DD; k++)
            a += (gcn_b2[k] + gin_b2[k]) * g_M[k * DD + c];
        g_c0[c] = a + g_c0a[c];
    }
}
__global__ void k_scan1(int n) {
    __shared__ int s[1024];
    int i = blockIdx.x * 1024 + threadIdx.x;
    int v = (i < n) ? g_cnt[i] : 0;
    s[threadIdx.x] = v;
    __syncthreads();
    for (int off = 1; off < 1024; off <<= 1) {
        int t = (threadIdx.x >= off) ? s[threadIdx.x - off] : 0;
        __syncthreads();
        s[threadIdx.x] += t;
        __syncthreads();
    }
    if (i < n) g_rowptr[i] = s[threadIdx.x] - v;   // exclusive within block
    if (threadIdx.x == 1023) g_blocksums[blockIdx.x] = s[1023];  // block total
}
// m3: blocks [0,gN) scan3 (smem-cached blocksum prefix); [gN, gN+192) wprep; [gN+192] c1
__global__ void k_m3(int n, int E, int gN, int nb,
                     const float* __restrict__ gcn_w1, const float* __restrict__ gin_b1) {
    int b = blockIdx.x;
    if (b < gN) {
        __shared__ int pref[104];
        if (threadIdx.x == 0) {
            int run = 0;
            for (int q = 0; q < nb; q++) { pref[q] = run; run += g_blocksums[q]; }
        }
        __syncthreads();
        int i = b * 256 + threadIdx.x;
        if (i < n) {
            g_rowptr[i] += pref[i >> 10];
            g_dinv[i] = rsqrtf((float)g_cnt[i] + 1.0f);
            g_cnt[i] = 0;
        }
        if (i == 0) g_rowptr[n] = E;
        return;
    }
    int bb = b - gN;
    if (bb < 192) {
        int mat = bb >> 6;
        int i = (bb & 63) * 256 + threadIdx.x;
        if (i >= 16384) return;
        int k = i >> 7, nn = i & 127;
        const float* W = (mat == 0) ? gcn_w1 : (mat == 1) ? g_Wg : g_Wn;
        float x = W[k * 128 + nn] * WSCALE;
        __half hi = __float2half_rn(x);
        __half lo = __float2half_rn(x - __half2float(hi));
        g_wimg[mat][0][nn * 128 + k] = hi;
        g_wimg[mat][1][nn * 128 + k] = lo;
    } else {
        int c = threadIdx.x;
        if (c < DD) {
            float a = 0.f;
            #pragma unroll 8
            for (int k = 0; k < DD; k++) a += gin_b1[k] * g_Wn2[k * DD + c];
            g_c1[c] = a;
        }
    }
}
__global__ void k_fill(const int* __restrict__ ei, int E, int n) {
    int e = blockIdx.x * blockDim.x + threadIdx.x;
    if (e < E) {
        int s = ei[e];
        int d = ei[E + e];
        if (s >= 0 && s < n && d >= 0 && d < n) {
            int pos = g_rowptr[d] + atomicAdd(&g_cnt[d], 1);
            g_col[pos] = s;
        }
    }
}
// after k_fill, g_cnt[i] == incoming degree again (used by l2 epilogue)

// ---------------- aggregation (warp per node; exact R12 versions) ----------------
// pass1 (fp32 X): P0 = aggW(X)+self, P1 = A1 = X + aggU(X)
__global__ void k_agg1(const float* __restrict__ X, int n) {
    int w = (blockIdx.x * blockDim.x + threadIdx.x) >> 5;
    if (w >= n) return;
    int lane = threadIdx.x & 31;
    const float4* Xv = (const float4*)X;
    int e = g_rowptr[w], end = g_rowptr[w + 1];
    float4 aw = make_float4(0, 0, 0, 0), au = make_float4(0, 0, 0, 0);
    for (; e + 4 <= end; e += 4) {
        int j0 = g_col[e], j1 = g_col[e + 1], j2 = g_col[e + 2], j3 = g_col[e + 3];
        float d0 = g_dinv[j0], d1 = g_dinv[j1], d2 = g_dinv[j2], d3 = g_dinv[j3];
        float4 v0 = Xv[(size_t)j0 * 32 + lane];
        float4 v1 = Xv[(size_t)j1 * 32 + lane];
        float4 v2 = Xv[(size_t)j2 * 32 + lane];
        float4 v3 = Xv[(size_t)j3 * 32 + lane];
        aw.x += d0 * v0.x + d1 * v1.x + d2 * v2.x + d3 * v3.x;
        aw.y += d0 * v0.y + d1 * v1.y + d2 * v2.y + d3 * v3.y;
        aw.z += d0 * v0.z + d1 * v1.z + d2 * v2.z + d3 * v3.z;
        aw.w += d0 * v0.w + d1 * v1.w + d2 * v2.w + d3 * v3.w;
        au.x += v0.x + v1.x + v2.x + v3.x;
        au.y += v0.y + v1.y + v2.y + v3.y;
        au.z += v0.z + v1.z + v2.z + v3.z;
        au.w += v0.w + v1.w + v2.w + v3.w;
    }
    for (; e < end; e++) {
        int j = g_col[e];
        float dj = g_dinv[j];
        float4 v = Xv[(size_t)j * 32 + lane];
        aw.x += dj * v.x; aw.y += dj * v.y; aw.z += dj * v.z; aw.w += dj * v.w;
        au.x += v.x;      au.y += v.y;      au.z += v.z;      au.w += v.w;
    }
    float di = g_dinv[w], dii = di * di;
    float4 xi = Xv[(size_t)w * 32 + lane];
    float4 ow, ou;
    ow.x = di * aw.x + dii * xi.x; ow.y = di * aw.y + dii * xi.y;
    ow.z = di * aw.z + dii * xi.z; ow.w = di * aw.w + dii * xi.w;
    ou.x = au.x + xi.x; ou.y = au.y + xi.y; ou.z = au.z + xi.z; ou.w = au.w + xi.w;
    size_t idx = (size_t)w * 128 + lane * 4;
    storeh4(g_Pf[0], idx, ow);
    storeh4(g_Pf[1], idx, ou);
}
// pass2: P0 = aggW(P2=h)+self, P3 = A2 = P1 + aggU(P1)
__global__ void k_agg2(int n) {
    int w = (blockIdx.x * blockDim.x + threadIdx.x) >> 5;
    if (w >= n) return;
    int lane = threadIdx.x & 31;
    int e = g_rowptr[w], end = g_rowptr[w + 1];
    float4 aw = make_float4(0, 0, 0, 0), au = make_float4(0, 0, 0, 0);
    for (; e + 4 <= end; e += 4) {
        int j0 = g_col[e], j1 = g_col[e + 1], j2 = g_col[e + 2], j3 = g_col[e + 3];
        float d0 = g_dinv[j0], d1 = g_dinv[j1], d2 = g_dinv[j2], d3 = g_dinv[j3];
        size_t i0 = (size_t)j0 * 128 + lane * 4, i1 = (size_t)j1 * 128 + lane * 4;
        size_t i2 = (size_t)j2 * 128 + lane * 4, i3 = (size_t)j3 * 128 + lane * 4;
        float4 h0 = loadh4(g_Pf[2], i0);
        float4 h1 = loadh4(g_Pf[2], i1);
        float4 h2 = loadh4(g_Pf[2], i2);
        float4 h3 = loadh4(g_Pf[2], i3);
        float4 a0 = loadh4(g_Pf[1], i0);
        float4 a1 = loadh4(g_Pf[1], i1);
        float4 a2 = loadh4(g_Pf[1], i2);
        float4 a3 = loadh4(g_Pf[1], i3);
        aw.x += d0 * h0.x + d1 * h1.x + d2 * h2.x + d3 * h3.x;
        aw.y += d0 * h0.y + d1 * h1.y + d2 * h2.y + d3 * h3.y;
        aw.z += d0 * h0.z + d1 * h1.z + d2 * h2.z + d3 * h3.z;
        aw.w += d0 * h0.w + d1 * h1.w + d2 * h2.w + d3 * h3.w;
        au.x += a0.x + a1.x + a2.x + a3.x;
        au.y += a0.y + a1.y + a2.y + a3.y;
        au.z += a0.z + a1.z + a2.z + a3.z;
        au.w += a0.w + a1.w + a2.w + a3.w;
    }
    for (; e < end; e++) {
        int j = g_col[e];
        float dj = g_dinv[j];
        size_t i0 = (size_t)j * 128 + lane * 4;
        float4 hv = loadh4(g_Pf[2], i0);
        float4 av = loadh4(g_Pf[1], i0);
        aw.x += dj * hv.x; aw.y += dj * hv.y; aw.z += dj * hv.z; aw.w += dj * hv.w;
        au.x += av.x;      au.y += av.y;      au.z += av.z;      au.w += av.w;
    }
    float di = g_dinv[w], dii = di * di;
    size_t iw = (size_t)w * 128 + lane * 4;
    float4 hi = loadh4(g_Pf[2], iw);
    float4 ai = loadh4(g_Pf[1], iw);
    float4 ow, ou;
    ow.x = di * aw.x + dii * hi.x; ow.y = di * aw.y + dii * hi.y;
    ow.z = di * aw.z + dii * hi.z; ow.w = di * aw.w + dii * hi.w;
    ou.x = au.x + ai.x; ou.y = au.y + ai.y; ou.z = au.z + ai.z; ou.w = au.w + ai.w;
    storeh4(g_Pf[0], iw, ow);
    storeh4(g_Pf[3], iw, ou);
}

// ---------------- pipelined fp16 warp-mma GEMM (exact R12 version) ----------------
template <bool RELU, bool DUAL, int INA1, int INA2, int OUTI, int W1I, int W2I,
          int BSEL, bool OUTF32>
__device__ __forceinline__ void tgemm_body(int bx, const float* bias_param,
                                           float* outp, int n, uint32_t sbase) {
    int tid = threadIdx.x, lane = tid & 31, wid = tid >> 5;
    int wm = wid & 3, wn = wid >> 2;
    int row0 = bx * 128;

    float acc[2][8][4];
    #pragma unroll
    for (int i = 0; i < 2; i++)
        #pragma unroll
        for (int j = 0; j < 8; j++)
            #pragma unroll
            for (int q = 0; q < 4; q++) acc[i][j][q] = 0.f;

    const int T = DUAL ? 16 : 8;
    int sr = tid >> 1, sp = tid & 1;
    uint32_t soff = swz(sr, sp);
    int sgr = row0 + sr;
    bool svalid = sgr < n;
    size_t s_asrc = (size_t)(svalid ? sgr : 0) * 128 + sp * 8;
    size_t s_wsrc = (size_t)sr * 128 + sp * 8;

    auto do_stage = [&](int c) {
        int pass = DUAL ? (c >> 3) : 0;
        int kc = c & 7, s = c & 1;
        const __half* A = g_Pf[pass ? INA2 : INA1];
        int wi = pass ? W2I : W1I;
        uint32_t b = sbase + s * 12288;
        size_t ka = s_asrc + kc * 16, kw = s_wsrc + kc * 16;
        cpasync16(b + soff,        A + ka, svalid ? 16 : 0);
        cpasync16(b + 4096 + soff, g_wimg[wi][0] + kw, 16);
        cpasync16(b + 8192 + soff, g_wimg[wi][1] + kw, 16);
    };

    do_stage(0);
    cp_commit();

    for (int c = 0; c < T; c++) {
        if (c + 1 < T) {
            do_stage(c + 1);
            cp_commit();
            cp_wait<1>();
        } else {
            cp_wait<0>();
        }
        __syncthreads();

        uint32_t b0 = sbase + (c & 1) * 12288;
        uint32_t a[2][4];
        #pragma unroll
        for (int mi = 0; mi < 2; mi++) {
            int row = wm * 32 + mi * 16 + (lane & 15);
            ldsm4(a[mi], b0 + swz(row, lane >> 4));
        }
        #pragma unroll
        for (int term = 0; term < 2; term++) {
            uint32_t wb = b0 + 4096 + term * 4096;
            uint32_t bf[8][2];
            #pragma unroll
            for (int q = 0; q < 4; q++) {
                int rown = wn * 64 + q * 16 + ((lane >> 4) << 3) + (lane & 7);
                uint32_t r4[4];
                ldsm4(r4, wb + swz(rown, (lane >> 3) & 1));
                bf[q * 2 + 0][0] = r4[0]; bf[q * 2 + 0][1] = r4[1];
                bf[q * 2 + 1][0] = r4[2]; bf[q * 2 + 1][1] = r4[3];
            }
            #pragma unroll
            for (int mi = 0; mi < 2; mi++)
                #pragma unroll
                for (int nj = 0; nj < 8; nj++)
                    mma_f16(acc[mi][nj], a[mi], bf[nj]);
        }
        __syncthreads();
    }

    // epilogue (descale by WINV, then bias)
    int rbase = row0 + wm * 32 + (lane >> 2);
    int cbase = wn * 64 + (lane & 3) * 2;
    #pragma unroll
    for (int mi = 0; mi < 2; mi++) {
        #pragma unroll
        for (int half = 0; half < 2; half++) {
            int gr = rbase + mi * 16 + half * 8;
            if (gr >= n) continue;
            float s = (BSEL == 3) ? (float)(g_cnt[gr] + 1) : 0.f;
            #pragma unroll
            for (int nj = 0; nj < 8; nj++) {
                int col = cbase + nj * 8;
                float v0, v1;
                if (BSEL == 3) {
                    v0 = acc[mi][nj][half * 2 + 0] * WINV + s * g_c1[col]     + g_c0[col];
                    v1 = acc[mi][nj][half * 2 + 1] * WINV + s * g_c1[col + 1] + g_c0[col + 1];
                } else {
                    v0 = acc[mi][nj][half * 2 + 0] * WINV + bias_param[col];
                    v1 = acc[mi][nj][half * 2 + 1] * WINV + bias_param[col + 1];
                }
                if (RELU) { v0 = fmaxf(v0, 0.f); v1 = fmaxf(v1, 0.f); }
                if (OUTF32) {
                    *(float2*)&outp[(size_t)gr * 128 + col] = make_float2(v0, v1);
                } else {
                    __half2 hh = __floats2half2_rn(v0, v1);
                    *(__half2*)&g_Pf[OUTI][(size_t)gr * 128 + col] = hh;
                }
            }
        }
    }
}

// layer-1 GCN: h = relu(P0 @ gcn_w1 + b1) -> P2 fp16
__global__ void __launch_bounds__(256, 2) k_tgemm_l1(const float* __restrict__ b1,
                                                     float* __restrict__ outp, int n) {
    __shared__ __align__(1024) unsigned char sbuf[2 * 12288];
    tgemm_body<true, false, 0, 0, 2, 0, 0, 0, false>(blockIdx.x, b1, outp, n, smem_u32(sbuf));
}
// layer-2 fused head: out = P0@Wg + P3@Wn + (cnt+1)*c1 + c0   (fp32 out)
__global__ void __launch_bounds__(256, 2) k_tgemm_l2(float* __restrict__ outp, int n) {
    __shared__ __align__(1024) unsigned char sbuf[2 * 12288];
    tgemm_body<false, true, 0, 3, 0, 1, 2, 3, true>(blockIdx.x, outp, outp, n, smem_u32(sbuf));
}

// ---------------- launch ----------------
extern "C" void kernel_launch(void* const* d_in, const int* in_sizes, int n_in,
                              void* d_out, int out_size) {
    const float* X      = (const float*)d_in[0];
    const int*   ei     = (const int*)d_in[1];
    const float* gcn_w1 = (const float*)d_in[2];
    const float* gcn_b1 = (const float*)d_in[3];
    const float* gcn_w2 = (const float*)d_in[4];
    const float* gcn_b2 = (const float*)d_in[5];
    const float* gin_w1 = (const float*)d_in[6];
    const float* gin_b1 = (const float*)d_in[7];
    const float* gin_w2 = (const float*)d_in[8];
    const float* gin_b2 = (const float*)d_in[9];
    const float* lin_w  = (const float*)d_in[10];
    const float* lin_b  = (const float*)d_in[11];
    const float* fc_w   = (const float*)d_in[12];
    const float* fc_b   = (const float*)d_in[13];
    float*       out    = (float*)d_out;

    int N = in_sizes[0] / DD;
    int E = in_sizes[1] / 2;

    int nb = (N + 1023) / 1024;
    int gN = (N + 255) / 256;
    int gE = (E + 255) / 256;
    int gW = (N + 7) / 8;
    int gG = (N + 127) / 128;

    // merged CSR + weight-folding chain (8 launches total)
    k_m1<<<gN + 2 * DD + 1, 256>>>(N, gN, lin_w, lin_b, fc_w, fc_b, gin_w1, gin_w2);
    k_m2<<<gE + 3 * DD + 1, 256>>>(ei, E, N, gE, gcn_w2, gin_w2, gcn_b2, gin_b2);
    k_scan1<<<nb, 1024>>>(N);
    k_m3<<<gN + 193, 256>>>(N, E, gN, nb, gcn_w1, gin_b1);
    k_fill<<<gE, 256>>>(ei, E, N);

    // layer 1
    k_agg1<<<gW, 256>>>(X, N);
    k_tgemm_l1<<<gG, 256>>>(gcn_b1, out, N);

    // layer 2
    k_agg2<<<gW, 256>>>(N);
    k_tgemm_l2<<<gG, 256>>>(out, N);
}